// round 2
// baseline (speedup 1.0000x reference)
#include <cuda_runtime.h>
#include <math.h>

// Problem constants (fixed shapes from reference)
#define T_TOK 1024
#define H_DIM 2048
#define I_DIM 1408
#define E_NUM 8

// ---------------- device scratch (no runtime allocation allowed) ----------------
__device__ int   g_count[E_NUM];
__device__ int   g_tok[E_NUM * T_TOK];
__device__ float g_wt [E_NUM * T_TOK];
// routed h = silu(g)*u, laid out per-expert with fixed stride T_TOK rows
__device__ float g_hroute[(size_t)E_NUM * T_TOK * I_DIM];   // ~46 MB
__device__ float g_hshared[(size_t)T_TOK * I_DIM];          // ~5.8 MB

// ---------------- zero kernel ----------------
__global__ void zero_kernel(float* __restrict__ out, int n) {
    int i = blockIdx.x * blockDim.x + threadIdx.x;
    if (i < n) out[i] = 0.0f;
    if (i < E_NUM) g_count[i] = 0;
}

// ---------------- routing: logits -> top2 -> softmax -> scatter ----------------
__global__ void routing_kernel(const float* __restrict__ x,
                               const float* __restrict__ gw) {
    int t = blockIdx.x * blockDim.x + threadIdx.x;
    if (t >= T_TOK) return;
    float logits[E_NUM];
#pragma unroll
    for (int e = 0; e < E_NUM; e++) logits[e] = 0.0f;
    const float* xr = x + (size_t)t * H_DIM;
    for (int h = 0; h < H_DIM; h += 4) {
        float4 xv = *(const float4*)(xr + h);
#pragma unroll
        for (int e = 0; e < E_NUM; e++) {
            const float* wr = gw + (size_t)e * H_DIM + h;
            logits[e] += xv.x * wr[0] + xv.y * wr[1] + xv.z * wr[2] + xv.w * wr[3];
        }
    }
    // top-2 (first occurrence wins on ties, matching top_k semantics)
    int i0 = 0;
#pragma unroll
    for (int e = 1; e < E_NUM; e++) if (logits[e] > logits[i0]) i0 = e;
    int i1 = -1;
#pragma unroll
    for (int e = 0; e < E_NUM; e++) {
        if (e == i0) continue;
        if (i1 < 0 || logits[e] > logits[i1]) i1 = e;
    }
    float l0 = logits[i0], l1 = logits[i1];
    float e1 = expf(l1 - l0);
    float inv = 1.0f / (1.0f + e1);
    float w0 = inv;            // softmax of (l0, l1)
    float w1 = e1 * inv;

    int s0 = atomicAdd(&g_count[i0], 1);
    g_tok[i0 * T_TOK + s0] = t;
    g_wt [i0 * T_TOK + s0] = w0;
    int s1 = atomicAdd(&g_count[i1], 1);
    g_tok[i1 * T_TOK + s1] = t;
    g_wt [i1 * T_TOK + s1] = w1;
}

// ---------------- fused gate+up GEMM with silu epilogue ----------------
// C[m][n] = sum_k A[m][k] * W[n][k]  (A gathered token rows, W is [I,H] row-major)
// 64x64 tile, BK=16, 256 threads, 4x4 microtile, dual accumulators (gate & up).
__global__ void gateup_kernel(const float* __restrict__ X,
                              const float* __restrict__ Wg,
                              const float* __restrict__ Wu,
                              float* __restrict__ Hout,
                              int routed) {
    __shared__ float As[16][65];
    __shared__ float Bg[16][65];
    __shared__ float Bu[16][65];

    int e = blockIdx.z;
    int count = routed ? g_count[e] : T_TOK;
    int m0 = blockIdx.y * 64;
    if (m0 >= count) return;
    int n0 = blockIdx.x * 64;

    const float* wgB = Wg + (size_t)e * I_DIM * H_DIM;
    const float* wuB = Wu + (size_t)e * I_DIM * H_DIM;

    int tid = threadIdx.x;
    int lr = tid >> 2;          // 0..63 : row within tile for loading
    int lc = (tid & 3) * 4;     // 0,4,8,12 : float4 column group

    int arow = m0 + lr;
    const float* aptr = nullptr;
    if (arow < count) {
        int t = routed ? g_tok[e * T_TOK + arow] : arow;
        aptr = X + (size_t)t * H_DIM;
    }
    const float* bgp = wgB + (size_t)(n0 + lr) * H_DIM;
    const float* bup = wuB + (size_t)(n0 + lr) * H_DIM;

    int tx = tid & 15, ty = tid >> 4;
    float accg[4][4] = {}, accu[4][4] = {};

    for (int k0 = 0; k0 < H_DIM; k0 += 16) {
        float4 av = make_float4(0.f, 0.f, 0.f, 0.f);
        if (aptr) av = *(const float4*)(aptr + k0 + lc);
        float4 gv = *(const float4*)(bgp + k0 + lc);
        float4 uv = *(const float4*)(bup + k0 + lc);
        As[lc + 0][lr] = av.x; As[lc + 1][lr] = av.y;
        As[lc + 2][lr] = av.z; As[lc + 3][lr] = av.w;
        Bg[lc + 0][lr] = gv.x; Bg[lc + 1][lr] = gv.y;
        Bg[lc + 2][lr] = gv.z; Bg[lc + 3][lr] = gv.w;
        Bu[lc + 0][lr] = uv.x; Bu[lc + 1][lr] = uv.y;
        Bu[lc + 2][lr] = uv.z; Bu[lc + 3][lr] = uv.w;
        __syncthreads();
#pragma unroll
        for (int kk = 0; kk < 16; kk++) {
            float a[4], b0[4], b1[4];
#pragma unroll
            for (int i = 0; i < 4; i++) a[i] = As[kk][ty * 4 + i];
#pragma unroll
            for (int j = 0; j < 4; j++) { b0[j] = Bg[kk][tx * 4 + j]; b1[j] = Bu[kk][tx * 4 + j]; }
#pragma unroll
            for (int i = 0; i < 4; i++)
#pragma unroll
                for (int j = 0; j < 4; j++) {
                    accg[i][j] += a[i] * b0[j];
                    accu[i][j] += a[i] * b1[j];
                }
        }
        __syncthreads();
    }

    size_t rowbase = routed ? (size_t)e * T_TOK : 0;
#pragma unroll
    for (int i = 0; i < 4; i++) {
        int m = m0 + ty * 4 + i;
        if (m >= count) continue;
        size_t ro = (rowbase + m) * (size_t)I_DIM + n0 + tx * 4;
#pragma unroll
        for (int j = 0; j < 4; j++) {
            float g = accg[i][j];
            float u = accu[i][j];
            float s = g / (1.0f + __expf(-g));   // silu
            Hout[ro + j] = s * u;
        }
    }
}

// ---------------- down GEMM with weighted atomic scatter ----------------
// out[t][n] += wt * sum_i H[m][i] * Wd[n][i]   (Wd is [H,I] row-major)
__global__ void down_kernel(const float* __restrict__ Hbuf,
                            const float* __restrict__ Wd,
                            float* __restrict__ out,
                            int routed) {
    __shared__ float As[16][65];
    __shared__ float Bs[16][65];

    int e = blockIdx.z;
    int count = routed ? g_count[e] : T_TOK;
    int m0 = blockIdx.y * 64;
    if (m0 >= count) return;
    int n0 = blockIdx.x * 64;

    const float* wdB = Wd + (size_t)e * H_DIM * I_DIM;

    int tid = threadIdx.x;
    int lr = tid >> 2;
    int lc = (tid & 3) * 4;

    int arow = m0 + lr;
    const float* aptr = nullptr;
    if (arow < count) {
        size_t rowbase = routed ? (size_t)e * T_TOK : 0;
        aptr = Hbuf + (rowbase + arow) * (size_t)I_DIM;
    }
    const float* bp = wdB + (size_t)(n0 + lr) * I_DIM;

    int tx = tid & 15, ty = tid >> 4;
    float acc[4][4] = {};

    for (int k0 = 0; k0 < I_DIM; k0 += 16) {
        float4 av = make_float4(0.f, 0.f, 0.f, 0.f);
        if (aptr) av = *(const float4*)(aptr + k0 + lc);
        float4 bv = *(const float4*)(bp + k0 + lc);
        As[lc + 0][lr] = av.x; As[lc + 1][lr] = av.y;
        As[lc + 2][lr] = av.z; As[lc + 3][lr] = av.w;
        Bs[lc + 0][lr] = bv.x; Bs[lc + 1][lr] = bv.y;
        Bs[lc + 2][lr] = bv.z; Bs[lc + 3][lr] = bv.w;
        __syncthreads();
#pragma unroll
        for (int kk = 0; kk < 16; kk++) {
            float a[4], b[4];
#pragma unroll
            for (int i = 0; i < 4; i++) a[i] = As[kk][ty * 4 + i];
#pragma unroll
            for (int j = 0; j < 4; j++) b[j] = Bs[kk][tx * 4 + j];
#pragma unroll
            for (int i = 0; i < 4; i++)
#pragma unroll
                for (int j = 0; j < 4; j++) acc[i][j] += a[i] * b[j];
        }
        __syncthreads();
    }

#pragma unroll
    for (int i = 0; i < 4; i++) {
        int m = m0 + ty * 4 + i;
        if (m >= count) continue;
        int t;
        float wt;
        if (routed) {
            t  = g_tok[e * T_TOK + m];
            wt = g_wt [e * T_TOK + m];
        } else {
            t = m; wt = 1.0f;
        }
        float* orow = out + (size_t)t * H_DIM + n0 + tx * 4;
#pragma unroll
        for (int j = 0; j < 4; j++) atomicAdd(&orow[j], wt * acc[i][j]);
    }
}

// ---------------- launch ----------------
extern "C" void kernel_launch(void* const* d_in, const int* in_sizes, int n_in,
                              void* d_out, int out_size) {
    const float* x   = (const float*)d_in[0];   // [1,1024,2048]
    const float* gw  = (const float*)d_in[1];   // [8,2048]
    const float* egw = (const float*)d_in[2];   // [8,1408,2048]
    const float* euw = (const float*)d_in[3];   // [8,1408,2048]
    const float* edw = (const float*)d_in[4];   // [8,2048,1408]
    const float* sgw = (const float*)d_in[5];   // [1408,2048]
    const float* suw = (const float*)d_in[6];   // [1408,2048]
    const float* sdw = (const float*)d_in[7];   // [2048,1408]
    float* out = (float*)d_out;                 // [1,1024,2048]

    int n_out = T_TOK * H_DIM;
    zero_kernel<<<(n_out + 255) / 256, 256>>>(out, n_out);
    routing_kernel<<<T_TOK / 256, 256>>>(x, gw);

    // routed experts
    {
        dim3 grid(I_DIM / 64, T_TOK / 64, E_NUM);
        gateup_kernel<<<grid, 256>>>(x, egw, euw, g_hroute, 1);
    }
    {
        dim3 grid(H_DIM / 64, T_TOK / 64, E_NUM);
        down_kernel<<<grid, 256>>>(g_hroute, edw, out, 1);
    }
    // shared expert
    {
        dim3 grid(I_DIM / 64, T_TOK / 64, 1);
        gateup_kernel<<<grid, 256>>>(x, sgw, suw, g_hshared, 0);
    }
    {
        dim3 grid(H_DIM / 64, T_TOK / 64, 1);
        down_kernel<<<grid, 256>>>(g_hshared, sdw, out, 0);
    }
}

// round 4
// speedup vs baseline: 1.1062x; 1.1062x over previous
#include <cuda_runtime.h>
#include <cuda_bf16.h>
#include <mma.h>
#include <stdint.h>
#include <math.h>

using namespace nvcuda;

#define T_TOK 1024
#define H_DIM 2048
#define I_DIM 1408
#define E_NUM 8
#define LDA   40   // smem leading dim (elems), row stride 80B (16B-aligned)

typedef wmma::fragment<wmma::matrix_a, 16, 16, 16, __nv_bfloat16, wmma::row_major> FragA;
typedef wmma::fragment<wmma::matrix_b, 16, 16, 16, __nv_bfloat16, wmma::col_major> FragB;
typedef wmma::fragment<wmma::accumulator, 16, 16, 16, float> FragC;

// ---------------- device scratch ----------------
__device__ int   g_count[E_NUM];
__device__ int   g_tok[E_NUM * T_TOK];
__device__ float g_wt [E_NUM * T_TOK];
__device__ float g_hroute[(size_t)E_NUM * T_TOK * I_DIM];
__device__ float g_hshared[(size_t)T_TOK * I_DIM];

// ---------------- helpers ----------------
__device__ __forceinline__ uint32_t b2u(__nv_bfloat162 h) { return *reinterpret_cast<uint32_t*>(&h); }

// 8 fp32 -> 8 bf16 hi (uint4) + 8 bf16 lo (uint4)
__device__ __forceinline__ void cvt8(const float4 a, const float4 b, uint4& hi, uint4& lo) {
    __nv_bfloat162 h0 = __floats2bfloat162_rn(a.x, a.y);
    __nv_bfloat162 h1 = __floats2bfloat162_rn(a.z, a.w);
    __nv_bfloat162 h2 = __floats2bfloat162_rn(b.x, b.y);
    __nv_bfloat162 h3 = __floats2bfloat162_rn(b.z, b.w);
    __nv_bfloat162 l0 = __floats2bfloat162_rn(a.x - __low2float(h0), a.y - __high2float(h0));
    __nv_bfloat162 l1 = __floats2bfloat162_rn(a.z - __low2float(h1), a.w - __high2float(h1));
    __nv_bfloat162 l2 = __floats2bfloat162_rn(b.x - __low2float(h2), b.y - __high2float(h2));
    __nv_bfloat162 l3 = __floats2bfloat162_rn(b.z - __low2float(h3), b.w - __high2float(h3));
    hi = make_uint4(b2u(h0), b2u(h1), b2u(h2), b2u(h3));
    lo = make_uint4(b2u(l0), b2u(l1), b2u(l2), b2u(l3));
}
// 4 fp32 -> 4 bf16 hi (uint2) + lo (uint2)
__device__ __forceinline__ void cvt4(const float4 a, uint2& hi, uint2& lo) {
    __nv_bfloat162 h0 = __floats2bfloat162_rn(a.x, a.y);
    __nv_bfloat162 h1 = __floats2bfloat162_rn(a.z, a.w);
    __nv_bfloat162 l0 = __floats2bfloat162_rn(a.x - __low2float(h0), a.y - __high2float(h0));
    __nv_bfloat162 l1 = __floats2bfloat162_rn(a.z - __low2float(h1), a.w - __high2float(h1));
    hi = make_uint2(b2u(h0), b2u(h1));
    lo = make_uint2(b2u(l0), b2u(l1));
}

// ---------------- zero + routing ----------------
__global__ void zero_kernel(float* __restrict__ out, int n) {
    int i = blockIdx.x * blockDim.x + threadIdx.x;
    if (i < n) out[i] = 0.0f;
    if (i < E_NUM) g_count[i] = 0;
}

__global__ void routing_kernel(const float* __restrict__ x, const float* __restrict__ gw) {
    int t = blockIdx.x * blockDim.x + threadIdx.x;
    if (t >= T_TOK) return;
    float logits[E_NUM];
#pragma unroll
    for (int e = 0; e < E_NUM; e++) logits[e] = 0.0f;
    const float* xr = x + (size_t)t * H_DIM;
    for (int h = 0; h < H_DIM; h += 4) {
        float4 xv = *(const float4*)(xr + h);
#pragma unroll
        for (int e = 0; e < E_NUM; e++) {
            const float* wr = gw + (size_t)e * H_DIM + h;
            logits[e] += xv.x * wr[0] + xv.y * wr[1] + xv.z * wr[2] + xv.w * wr[3];
        }
    }
    int i0 = 0;
#pragma unroll
    for (int e = 1; e < E_NUM; e++) if (logits[e] > logits[i0]) i0 = e;
    int i1 = -1;
#pragma unroll
    for (int e = 0; e < E_NUM; e++) {
        if (e == i0) continue;
        if (i1 < 0 || logits[e] > logits[i1]) i1 = e;
    }
    float e1 = expf(logits[i1] - logits[i0]);
    float inv = 1.0f / (1.0f + e1);
    int s0 = atomicAdd(&g_count[i0], 1);
    g_tok[i0 * T_TOK + s0] = t;  g_wt[i0 * T_TOK + s0] = inv;
    int s1 = atomicAdd(&g_count[i1], 1);
    g_tok[i1 * T_TOK + s1] = t;  g_wt[i1 * T_TOK + s1] = e1 * inv;
}

// ---------------- gate+up GEMM (wmma bf16x3, fused silu) ----------------
// BM=128 BN=64 BK=32, 512 threads (16 warps 4x4), warp tile 32x16 per matrix.
// smem: Ah 10240 | Al 10240 | Gh 5120 | Gl 5120 | Uh 5120 | Ul 5120 = 40960B
#define GU_OFF_AL 10240
#define GU_OFF_GH 20480
#define GU_OFF_GL 25600
#define GU_OFF_UH 30720
#define GU_OFF_UL 35840

__global__ void __launch_bounds__(512, 1)
gu_kernel(const float* __restrict__ X, const float* __restrict__ Wg,
          const float* __restrict__ Wu, float* __restrict__ Hout, int routed) {
    __shared__ char sm[40960];
    const int e = blockIdx.z;
    const int count = routed ? g_count[e] : T_TOK;
    const int m0 = blockIdx.y * 128;
    if (m0 >= count) return;
    const int n0 = blockIdx.x * 64;

    const int tid = threadIdx.x;
    const int wid = tid >> 5;
    const int wm = wid >> 2, wn = wid & 3;

    // A loader: row = tid>>2 (128 rows), quarter = tid&3 -> 8 fp32
    const int ar = tid >> 2, aq = tid & 3;
    const int mrow = m0 + ar;
    const bool aval = mrow < count;
    int tok = 0;
    if (aval) tok = routed ? g_tok[e * T_TOK + mrow] : mrow;
    const float4* ap = (const float4*)(X + (size_t)tok * H_DIM) + aq * 2;
    // B loaders: row n = tid>>3 (64 rows), oct = tid&7 -> 4 fp32
    const int bn = tid >> 3, bo = tid & 7;
    const float4* gp = (const float4*)(Wg + (size_t)e * I_DIM * H_DIM + (size_t)(n0 + bn) * H_DIM) + bo;
    const float4* up = (const float4*)(Wu + (size_t)e * I_DIM * H_DIM + (size_t)(n0 + bn) * H_DIM) + bo;

    const uint32_t aoff = (uint32_t)(ar * LDA + aq * 8) * 2;
    const uint32_t boff = (uint32_t)(bn * LDA + bo * 4) * 2;

    FragC accg[2], accu[2];
#pragma unroll
    for (int i = 0; i < 2; i++) { wmma::fill_fragment(accg[i], 0.0f); wmma::fill_fragment(accu[i], 0.0f); }

    float4 ra0, ra1, rg, ru;
    ra0 = ap[0]; ra1 = ap[1]; rg = gp[0]; ru = up[0];

    const __nv_bfloat16* sAh = (const __nv_bfloat16*)sm;
    const __nv_bfloat16* sAl = (const __nv_bfloat16*)(sm + GU_OFF_AL);
    const __nv_bfloat16* sGh = (const __nv_bfloat16*)(sm + GU_OFF_GH);
    const __nv_bfloat16* sGl = (const __nv_bfloat16*)(sm + GU_OFF_GL);
    const __nv_bfloat16* sUh = (const __nv_bfloat16*)(sm + GU_OFF_UH);
    const __nv_bfloat16* sUl = (const __nv_bfloat16*)(sm + GU_OFF_UL);

    for (int kk = 0; kk < 64; kk++) {
        if (kk) __syncthreads();
        {   // convert + store current chunk
            uint4 hi, lo;
            cvt8(ra0, ra1, hi, lo);
            *(uint4*)(sm + aoff) = hi;
            *(uint4*)(sm + GU_OFF_AL + aoff) = lo;
            uint2 h2, l2;
            cvt4(rg, h2, l2);
            *(uint2*)(sm + GU_OFF_GH + boff) = h2;
            *(uint2*)(sm + GU_OFF_GL + boff) = l2;
            cvt4(ru, h2, l2);
            *(uint2*)(sm + GU_OFF_UH + boff) = h2;
            *(uint2*)(sm + GU_OFF_UL + boff) = l2;
        }
        __syncthreads();
        if (kk < 63) {  // prefetch next chunk
            const float4* a4 = ap + (kk + 1) * 8;
            ra0 = a4[0]; ra1 = a4[1];
            rg = gp[(kk + 1) * 8]; ru = up[(kk + 1) * 8];
        }
        // compute
#pragma unroll
        for (int ks = 0; ks < 2; ks++) {
            const int k0 = ks * 16;
            FragA ah[2], al[2];
#pragma unroll
            for (int mi = 0; mi < 2; mi++) {
                const int rbase = (wm * 32 + mi * 16) * LDA + k0;
                wmma::load_matrix_sync(ah[mi], sAh + rbase, LDA);
                wmma::load_matrix_sync(al[mi], sAl + rbase, LDA);
            }
            const int cbase = (wn * 16) * LDA + k0;
            FragB bh, bl;
            wmma::load_matrix_sync(bh, sGh + cbase, LDA);
            wmma::load_matrix_sync(bl, sGl + cbase, LDA);
#pragma unroll
            for (int mi = 0; mi < 2; mi++) {
                wmma::mma_sync(accg[mi], ah[mi], bh, accg[mi]);
                wmma::mma_sync(accg[mi], ah[mi], bl, accg[mi]);
                wmma::mma_sync(accg[mi], al[mi], bh, accg[mi]);
            }
            wmma::load_matrix_sync(bh, sUh + cbase, LDA);
            wmma::load_matrix_sync(bl, sUl + cbase, LDA);
#pragma unroll
            for (int mi = 0; mi < 2; mi++) {
                wmma::mma_sync(accu[mi], ah[mi], bh, accu[mi]);
                wmma::mma_sync(accu[mi], ah[mi], bl, accu[mi]);
                wmma::mma_sync(accu[mi], al[mi], bh, accu[mi]);
            }
        }
    }

    // epilogue: silu(g)*u, store directly to Hout (rows >= count are never read)
    const size_t rowbase = routed ? (size_t)e * T_TOK : 0;
#pragma unroll
    for (int mi = 0; mi < 2; mi++) {
#pragma unroll
        for (int i = 0; i < accg[mi].num_elements; i++) {
            float g = accg[mi].x[i];
            float u = accu[mi].x[i];
            accg[mi].x[i] = (g / (1.0f + __expf(-g))) * u;
        }
        const int m = m0 + wm * 32 + mi * 16;
        wmma::store_matrix_sync(Hout + (rowbase + m) * (size_t)I_DIM + n0 + wn * 16,
                                accg[mi], I_DIM, wmma::mem_row_major);
    }
}

// ---------------- down GEMM (wmma bf16x3, weighted atomic scatter) ----------------
// BM=128 BN=64 BK=32, K=1408 (44 chunks)
// smem tiles: Ah 10240 | Al 10240 | Bh 5120 | Bl 5120 = 30720B ; epilogue reuses as 128x68 fp32 (34816B)
#define DN_OFF_AL 10240
#define DN_OFF_BH 20480
#define DN_OFF_BL 25600
#define DN_LDO 68

__global__ void __launch_bounds__(512, 1)
dn_kernel(const float* __restrict__ Hbuf, const float* __restrict__ Wd,
          float* __restrict__ out, int routed) {
    __shared__ char sm[34816];
    const int e = blockIdx.z;
    const int count = routed ? g_count[e] : T_TOK;
    const int m0 = blockIdx.y * 128;
    if (m0 >= count) return;
    const int n0 = blockIdx.x * 64;

    const int tid = threadIdx.x;
    const int wid = tid >> 5;
    const int wm = wid >> 2, wn = wid & 3;

    const int ar = tid >> 2, aq = tid & 3;
    const int mrow = m0 + ar;
    const bool aval = mrow < count;
    const size_t rowbase = routed ? (size_t)e * T_TOK : 0;
    const float4* ap = (const float4*)(Hbuf + (rowbase + (aval ? mrow : m0)) * (size_t)I_DIM) + aq * 2;
    const int bn = tid >> 3, bo = tid & 7;
    const float4* bp = (const float4*)(Wd + (size_t)e * H_DIM * I_DIM + (size_t)(n0 + bn) * I_DIM) + bo;

    const uint32_t aoff = (uint32_t)(ar * LDA + aq * 8) * 2;
    const uint32_t boff = (uint32_t)(bn * LDA + bo * 4) * 2;

    FragC acc[2];
#pragma unroll
    for (int i = 0; i < 2; i++) wmma::fill_fragment(acc[i], 0.0f);

    float4 ra0, ra1, rb;
    ra0 = ap[0]; ra1 = ap[1]; rb = bp[0];

    const __nv_bfloat16* sAh = (const __nv_bfloat16*)sm;
    const __nv_bfloat16* sAl = (const __nv_bfloat16*)(sm + DN_OFF_AL);
    const __nv_bfloat16* sBh = (const __nv_bfloat16*)(sm + DN_OFF_BH);
    const __nv_bfloat16* sBl = (const __nv_bfloat16*)(sm + DN_OFF_BL);

    for (int kk = 0; kk < 44; kk++) {
        if (kk) __syncthreads();
        {
            uint4 hi, lo;
            cvt8(ra0, ra1, hi, lo);
            *(uint4*)(sm + aoff) = hi;
            *(uint4*)(sm + DN_OFF_AL + aoff) = lo;
            uint2 h2, l2;
            cvt4(rb, h2, l2);
            *(uint2*)(sm + DN_OFF_BH + boff) = h2;
            *(uint2*)(sm + DN_OFF_BL + boff) = l2;
        }
        __syncthreads();
        if (kk < 43) {
            const float4* a4 = ap + (kk + 1) * 8;
            ra0 = a4[0]; ra1 = a4[1];
            rb = bp[(kk + 1) * 8];
        }
#pragma unroll
        for (int ks = 0; ks < 2; ks++) {
            const int k0 = ks * 16;
            FragA ah[2], al[2];
#pragma unroll
            for (int mi = 0; mi < 2; mi++) {
                const int rbase = (wm * 32 + mi * 16) * LDA + k0;
                wmma::load_matrix_sync(ah[mi], sAh + rbase, LDA);
                wmma::load_matrix_sync(al[mi], sAl + rbase, LDA);
            }
            const int cbase = (wn * 16) * LDA + k0;
            FragB bh, bl;
            wmma::load_matrix_sync(bh, sBh + cbase, LDA);
            wmma::load_matrix_sync(bl, sBl + cbase, LDA);
#pragma unroll
            for (int mi = 0; mi < 2; mi++) {
                wmma::mma_sync(acc[mi], ah[mi], bh, acc[mi]);
                wmma::mma_sync(acc[mi], ah[mi], bl, acc[mi]);
                wmma::mma_sync(acc[mi], al[mi], bh, acc[mi]);
            }
        }
    }

    // epilogue: stage to smem, then weighted atomic scatter
    __syncthreads();
    float* sOut = (float*)sm;
#pragma unroll
    for (int mi = 0; mi < 2; mi++) {
        wmma::store_matrix_sync(sOut + (wm * 32 + mi * 16) * DN_LDO + wn * 16,
                                acc[mi], DN_LDO, wmma::mem_row_major);
    }
    __syncthreads();
    const int r = tid >> 2, c0 = (tid & 3) * 16;
    const int m = m0 + r;
    if (m < count) {
        int t; float wt;
        if (routed) { t = g_tok[e * T_TOK + m]; wt = g_wt[e * T_TOK + m]; }
        else        { t = m; wt = 1.0f; }
        float* orow = out + (size_t)t * H_DIM + n0 + c0;
        const float* srow = sOut + r * DN_LDO + c0;
#pragma unroll
        for (int j = 0; j < 16; j++) atomicAdd(&orow[j], wt * srow[j]);
    }
}

// ---------------- launch ----------------
extern "C" void kernel_launch(void* const* d_in, const int* in_sizes, int n_in,
                              void* d_out, int out_size) {
    const float* x   = (const float*)d_in[0];
    const float* gw  = (const float*)d_in[1];
    const float* egw = (const float*)d_in[2];
    const float* euw = (const float*)d_in[3];
    const float* edw = (const float*)d_in[4];
    const float* sgw = (const float*)d_in[5];
    const float* suw = (const float*)d_in[6];
    const float* sdw = (const float*)d_in[7];
    float* out = (float*)d_out;

    int n_out = T_TOK * H_DIM;
    zero_kernel<<<(n_out + 255) / 256, 256>>>(out, n_out);
    routing_kernel<<<T_TOK / 256, 256>>>(x, gw);

    gu_kernel<<<dim3(I_DIM / 64, T_TOK / 128, E_NUM), 512>>>(x, egw, euw, g_hroute, 1);
    dn_kernel<<<dim3(H_DIM / 64, T_TOK / 128, E_NUM), 512>>>(g_hroute, edw, out, 1);
    gu_kernel<<<dim3(I_DIM / 64, T_TOK / 128, 1), 512>>>(x, sgw, suw, g_hshared, 0);
    dn_kernel<<<dim3(H_DIM / 64, T_TOK / 128, 1), 512>>>(g_hshared, sdw, out, 0);
}

// round 5
// speedup vs baseline: 1.1090x; 1.0026x over previous
#include <cuda_runtime.h>
#include <cuda_bf16.h>
#include <mma.h>
#include <stdint.h>
#include <math.h>

using namespace nvcuda;

#define T_TOK 1024
#define H_DIM 2048
#define I_DIM 1408
#define E_NUM 8
#define LDA   40   // smem leading dim (elems), row stride 80B (16B-aligned)

typedef wmma::fragment<wmma::matrix_a, 16, 16, 16, __nv_bfloat16, wmma::row_major> FragA;
typedef wmma::fragment<wmma::matrix_b, 16, 16, 16, __nv_bfloat16, wmma::col_major> FragB;
typedef wmma::fragment<wmma::accumulator, 16, 16, 16, float> FragC;

// ---------------- device scratch ----------------
__device__ int   g_count[E_NUM];
__device__ int   g_tok[E_NUM * T_TOK];
__device__ float g_wt [E_NUM * T_TOK];
__device__ float g_hroute[(size_t)E_NUM * T_TOK * I_DIM];
__device__ float g_hshared[(size_t)T_TOK * I_DIM];

// ---------------- helpers ----------------
__device__ __forceinline__ uint32_t b2u(__nv_bfloat162 h) { return *reinterpret_cast<uint32_t*>(&h); }

// 8 fp32 -> 8 bf16 hi (uint4) + 8 bf16 lo (uint4)
__device__ __forceinline__ void cvt8(const float4 a, const float4 b, uint4& hi, uint4& lo) {
    __nv_bfloat162 h0 = __floats2bfloat162_rn(a.x, a.y);
    __nv_bfloat162 h1 = __floats2bfloat162_rn(a.z, a.w);
    __nv_bfloat162 h2 = __floats2bfloat162_rn(b.x, b.y);
    __nv_bfloat162 h3 = __floats2bfloat162_rn(b.z, b.w);
    __nv_bfloat162 l0 = __floats2bfloat162_rn(a.x - __low2float(h0), a.y - __high2float(h0));
    __nv_bfloat162 l1 = __floats2bfloat162_rn(a.z - __low2float(h1), a.w - __high2float(h1));
    __nv_bfloat162 l2 = __floats2bfloat162_rn(b.x - __low2float(h2), b.y - __high2float(h2));
    __nv_bfloat162 l3 = __floats2bfloat162_rn(b.z - __low2float(h3), b.w - __high2float(h3));
    hi = make_uint4(b2u(h0), b2u(h1), b2u(h2), b2u(h3));
    lo = make_uint4(b2u(l0), b2u(l1), b2u(l2), b2u(l3));
}
// 4 fp32 -> 4 bf16 hi (uint2) + lo (uint2)
__device__ __forceinline__ void cvt4(const float4 a, uint2& hi, uint2& lo) {
    __nv_bfloat162 h0 = __floats2bfloat162_rn(a.x, a.y);
    __nv_bfloat162 h1 = __floats2bfloat162_rn(a.z, a.w);
    __nv_bfloat162 l0 = __floats2bfloat162_rn(a.x - __low2float(h0), a.y - __high2float(h0));
    __nv_bfloat162 l1 = __floats2bfloat162_rn(a.z - __low2float(h1), a.w - __high2float(h1));
    hi = make_uint2(b2u(h0), b2u(h1));
    lo = make_uint2(b2u(l0), b2u(l1));
}

// ---------------- zero + routing ----------------
__global__ void zero_kernel(float* __restrict__ out, int n) {
    int i = blockIdx.x * blockDim.x + threadIdx.x;
    if (i < n) out[i] = 0.0f;
    if (i < E_NUM) g_count[i] = 0;
}

__global__ void routing_kernel(const float* __restrict__ x, const float* __restrict__ gw) {
    int t = blockIdx.x * blockDim.x + threadIdx.x;
    if (t >= T_TOK) return;
    float logits[E_NUM];
#pragma unroll
    for (int e = 0; e < E_NUM; e++) logits[e] = 0.0f;
    const float* xr = x + (size_t)t * H_DIM;
    for (int h = 0; h < H_DIM; h += 4) {
        float4 xv = *(const float4*)(xr + h);
#pragma unroll
        for (int e = 0; e < E_NUM; e++) {
            const float* wr = gw + (size_t)e * H_DIM + h;
            logits[e] += xv.x * wr[0] + xv.y * wr[1] + xv.z * wr[2] + xv.w * wr[3];
        }
    }
    int i0 = 0;
#pragma unroll
    for (int e = 1; e < E_NUM; e++) if (logits[e] > logits[i0]) i0 = e;
    int i1 = -1;
#pragma unroll
    for (int e = 0; e < E_NUM; e++) {
        if (e == i0) continue;
        if (i1 < 0 || logits[e] > logits[i1]) i1 = e;
    }
    float e1 = expf(logits[i1] - logits[i0]);
    float inv = 1.0f / (1.0f + e1);
    int s0 = atomicAdd(&g_count[i0], 1);
    g_tok[i0 * T_TOK + s0] = t;  g_wt[i0 * T_TOK + s0] = inv;
    int s1 = atomicAdd(&g_count[i1], 1);
    g_tok[i1 * T_TOK + s1] = t;  g_wt[i1 * T_TOK + s1] = e1 * inv;
}

// ---------------- gate+up GEMM (wmma bf16x3, fused silu) ----------------
// BM=128 BN=64 BK=32, 512 threads (16 warps 4x4), warp tile 32x16 per matrix.
// smem: Ah 10240 | Al 10240 | Gh 5120 | Gl 5120 | Uh 5120 | Ul 5120 = 40960B
#define GU_OFF_AL 10240
#define GU_OFF_GH 20480
#define GU_OFF_GL 25600
#define GU_OFF_UH 30720
#define GU_OFF_UL 35840

__global__ void __launch_bounds__(512, 1)
gu_kernel(const float* __restrict__ X, const float* __restrict__ Wg,
          const float* __restrict__ Wu, float* __restrict__ Hout, int routed) {
    __shared__ char sm[40960];
    const int e = blockIdx.z;
    const int count = routed ? g_count[e] : T_TOK;
    const int m0 = blockIdx.y * 128;
    if (m0 >= count) return;
    const int n0 = blockIdx.x * 64;

    const int tid = threadIdx.x;
    const int wid = tid >> 5;
    const int wm = wid >> 2, wn = wid & 3;

    // A loader: row = tid>>2 (128 rows), quarter = tid&3 -> 8 fp32
    const int ar = tid >> 2, aq = tid & 3;
    const int mrow = m0 + ar;
    const bool aval = mrow < count;
    int tok = 0;
    if (aval) tok = routed ? g_tok[e * T_TOK + mrow] : mrow;
    const float4* ap = (const float4*)(X + (size_t)tok * H_DIM) + aq * 2;
    // B loaders: row n = tid>>3 (64 rows), oct = tid&7 -> 4 fp32
    const int bn = tid >> 3, bo = tid & 7;
    const float4* gp = (const float4*)(Wg + (size_t)e * I_DIM * H_DIM + (size_t)(n0 + bn) * H_DIM) + bo;
    const float4* up = (const float4*)(Wu + (size_t)e * I_DIM * H_DIM + (size_t)(n0 + bn) * H_DIM) + bo;

    const uint32_t aoff = (uint32_t)(ar * LDA + aq * 8) * 2;
    const uint32_t boff = (uint32_t)(bn * LDA + bo * 4) * 2;

    FragC accg[2], accu[2];
#pragma unroll
    for (int i = 0; i < 2; i++) { wmma::fill_fragment(accg[i], 0.0f); wmma::fill_fragment(accu[i], 0.0f); }

    float4 ra0, ra1, rg, ru;
    ra0 = ap[0]; ra1 = ap[1]; rg = gp[0]; ru = up[0];

    const __nv_bfloat16* sAh = (const __nv_bfloat16*)sm;
    const __nv_bfloat16* sAl = (const __nv_bfloat16*)(sm + GU_OFF_AL);
    const __nv_bfloat16* sGh = (const __nv_bfloat16*)(sm + GU_OFF_GH);
    const __nv_bfloat16* sGl = (const __nv_bfloat16*)(sm + GU_OFF_GL);
    const __nv_bfloat16* sUh = (const __nv_bfloat16*)(sm + GU_OFF_UH);
    const __nv_bfloat16* sUl = (const __nv_bfloat16*)(sm + GU_OFF_UL);

    for (int kk = 0; kk < 64; kk++) {
        if (kk) __syncthreads();
        {   // convert + store current chunk
            uint4 hi, lo;
            cvt8(ra0, ra1, hi, lo);
            *(uint4*)(sm + aoff) = hi;
            *(uint4*)(sm + GU_OFF_AL + aoff) = lo;
            uint2 h2, l2;
            cvt4(rg, h2, l2);
            *(uint2*)(sm + GU_OFF_GH + boff) = h2;
            *(uint2*)(sm + GU_OFF_GL + boff) = l2;
            cvt4(ru, h2, l2);
            *(uint2*)(sm + GU_OFF_UH + boff) = h2;
            *(uint2*)(sm + GU_OFF_UL + boff) = l2;
        }
        __syncthreads();
        if (kk < 63) {  // prefetch next chunk
            const float4* a4 = ap + (kk + 1) * 8;
            ra0 = a4[0]; ra1 = a4[1];
            rg = gp[(kk + 1) * 8]; ru = up[(kk + 1) * 8];
        }
        // compute
#pragma unroll
        for (int ks = 0; ks < 2; ks++) {
            const int k0 = ks * 16;
            FragA ah[2], al[2];
#pragma unroll
            for (int mi = 0; mi < 2; mi++) {
                const int rbase = (wm * 32 + mi * 16) * LDA + k0;
                wmma::load_matrix_sync(ah[mi], sAh + rbase, LDA);
                wmma::load_matrix_sync(al[mi], sAl + rbase, LDA);
            }
            const int cbase = (wn * 16) * LDA + k0;
            FragB bh, bl;
            wmma::load_matrix_sync(bh, sGh + cbase, LDA);
            wmma::load_matrix_sync(bl, sGl + cbase, LDA);
#pragma unroll
            for (int mi = 0; mi < 2; mi++) {
                wmma::mma_sync(accg[mi], ah[mi], bh, accg[mi]);
                wmma::mma_sync(accg[mi], ah[mi], bl, accg[mi]);
                wmma::mma_sync(accg[mi], al[mi], bh, accg[mi]);
            }
            wmma::load_matrix_sync(bh, sUh + cbase, LDA);
            wmma::load_matrix_sync(bl, sUl + cbase, LDA);
#pragma unroll
            for (int mi = 0; mi < 2; mi++) {
                wmma::mma_sync(accu[mi], ah[mi], bh, accu[mi]);
                wmma::mma_sync(accu[mi], ah[mi], bl, accu[mi]);
                wmma::mma_sync(accu[mi], al[mi], bh, accu[mi]);
            }
        }
    }

    // epilogue: silu(g)*u, store directly to Hout (rows >= count are never read)
    const size_t rowbase = routed ? (size_t)e * T_TOK : 0;
#pragma unroll
    for (int mi = 0; mi < 2; mi++) {
#pragma unroll
        for (int i = 0; i < accg[mi].num_elements; i++) {
            float g = accg[mi].x[i];
            float u = accu[mi].x[i];
            accg[mi].x[i] = (g / (1.0f + __expf(-g))) * u;
        }
        const int m = m0 + wm * 32 + mi * 16;
        wmma::store_matrix_sync(Hout + (rowbase + m) * (size_t)I_DIM + n0 + wn * 16,
                                accg[mi], I_DIM, wmma::mem_row_major);
    }
}

// ---------------- down GEMM (wmma bf16x3, weighted atomic scatter) ----------------
// BM=128 BN=64 BK=32, K=1408 (44 chunks)
// smem tiles: Ah 10240 | Al 10240 | Bh 5120 | Bl 5120 = 30720B ; epilogue reuses as 128x68 fp32 (34816B)
#define DN_OFF_AL 10240
#define DN_OFF_BH 20480
#define DN_OFF_BL 25600
#define DN_LDO 68

__global__ void __launch_bounds__(512, 1)
dn_kernel(const float* __restrict__ Hbuf, const float* __restrict__ Wd,
          float* __restrict__ out, int routed) {
    __shared__ char sm[34816];
    const int e = blockIdx.z;
    const int count = routed ? g_count[e] : T_TOK;
    const int m0 = blockIdx.y * 128;
    if (m0 >= count) return;
    const int n0 = blockIdx.x * 64;

    const int tid = threadIdx.x;
    const int wid = tid >> 5;
    const int wm = wid >> 2, wn = wid & 3;

    const int ar = tid >> 2, aq = tid & 3;
    const int mrow = m0 + ar;
    const bool aval = mrow < count;
    const size_t rowbase = routed ? (size_t)e * T_TOK : 0;
    const float4* ap = (const float4*)(Hbuf + (rowbase + (aval ? mrow : m0)) * (size_t)I_DIM) + aq * 2;
    const int bn = tid >> 3, bo = tid & 7;
    const float4* bp = (const float4*)(Wd + (size_t)e * H_DIM * I_DIM + (size_t)(n0 + bn) * I_DIM) + bo;

    const uint32_t aoff = (uint32_t)(ar * LDA + aq * 8) * 2;
    const uint32_t boff = (uint32_t)(bn * LDA + bo * 4) * 2;

    FragC acc[2];
#pragma unroll
    for (int i = 0; i < 2; i++) wmma::fill_fragment(acc[i], 0.0f);

    float4 ra0, ra1, rb;
    ra0 = ap[0]; ra1 = ap[1]; rb = bp[0];

    const __nv_bfloat16* sAh = (const __nv_bfloat16*)sm;
    const __nv_bfloat16* sAl = (const __nv_bfloat16*)(sm + DN_OFF_AL);
    const __nv_bfloat16* sBh = (const __nv_bfloat16*)(sm + DN_OFF_BH);
    const __nv_bfloat16* sBl = (const __nv_bfloat16*)(sm + DN_OFF_BL);

    for (int kk = 0; kk < 44; kk++) {
        if (kk) __syncthreads();
        {
            uint4 hi, lo;
            cvt8(ra0, ra1, hi, lo);
            *(uint4*)(sm + aoff) = hi;
            *(uint4*)(sm + DN_OFF_AL + aoff) = lo;
            uint2 h2, l2;
            cvt4(rb, h2, l2);
            *(uint2*)(sm + DN_OFF_BH + boff) = h2;
            *(uint2*)(sm + DN_OFF_BL + boff) = l2;
        }
        __syncthreads();
        if (kk < 43) {
            const float4* a4 = ap + (kk + 1) * 8;
            ra0 = a4[0]; ra1 = a4[1];
            rb = bp[(kk + 1) * 8];
        }
#pragma unroll
        for (int ks = 0; ks < 2; ks++) {
            const int k0 = ks * 16;
            FragA ah[2], al[2];
#pragma unroll
            for (int mi = 0; mi < 2; mi++) {
                const int rbase = (wm * 32 + mi * 16) * LDA + k0;
                wmma::load_matrix_sync(ah[mi], sAh + rbase, LDA);
                wmma::load_matrix_sync(al[mi], sAl + rbase, LDA);
            }
            const int cbase = (wn * 16) * LDA + k0;
            FragB bh, bl;
            wmma::load_matrix_sync(bh, sBh + cbase, LDA);
            wmma::load_matrix_sync(bl, sBl + cbase, LDA);
#pragma unroll
            for (int mi = 0; mi < 2; mi++) {
                wmma::mma_sync(acc[mi], ah[mi], bh, acc[mi]);
                wmma::mma_sync(acc[mi], ah[mi], bl, acc[mi]);
                wmma::mma_sync(acc[mi], al[mi], bh, acc[mi]);
            }
        }
    }

    // epilogue: stage to smem, then weighted atomic scatter
    __syncthreads();
    float* sOut = (float*)sm;
#pragma unroll
    for (int mi = 0; mi < 2; mi++) {
        wmma::store_matrix_sync(sOut + (wm * 32 + mi * 16) * DN_LDO + wn * 16,
                                acc[mi], DN_LDO, wmma::mem_row_major);
    }
    __syncthreads();
    const int r = tid >> 2, c0 = (tid & 3) * 16;
    const int m = m0 + r;
    if (m < count) {
        int t; float wt;
        if (routed) { t = g_tok[e * T_TOK + m]; wt = g_wt[e * T_TOK + m]; }
        else        { t = m; wt = 1.0f; }
        float* orow = out + (size_t)t * H_DIM + n0 + c0;
        const float* srow = sOut + r * DN_LDO + c0;
#pragma unroll
        for (int j = 0; j < 16; j++) atomicAdd(&orow[j], wt * srow[j]);
    }
}

// ---------------- launch ----------------
extern "C" void kernel_launch(void* const* d_in, const int* in_sizes, int n_in,
                              void* d_out, int out_size) {
    const float* x   = (const float*)d_in[0];
    const float* gw  = (const float*)d_in[1];
    const float* egw = (const float*)d_in[2];
    const float* euw = (const float*)d_in[3];
    const float* edw = (const float*)d_in[4];
    const float* sgw = (const float*)d_in[5];
    const float* suw = (const float*)d_in[6];
    const float* sdw = (const float*)d_in[7];
    float* out = (float*)d_out;

    int n_out = T_TOK * H_DIM;
    zero_kernel<<<(n_out + 255) / 256, 256>>>(out, n_out);
    routing_kernel<<<T_TOK / 256, 256>>>(x, gw);

    gu_kernel<<<dim3(I_DIM / 64, T_TOK / 128, E_NUM), 512>>>(x, egw, euw, g_hroute, 1);
    dn_kernel<<<dim3(H_DIM / 64, T_TOK / 128, E_NUM), 512>>>(g_hroute, edw, out, 1);
    gu_kernel<<<dim3(I_DIM / 64, T_TOK / 128, 1), 512>>>(x, sgw, suw, g_hshared, 0);
    dn_kernel<<<dim3(H_DIM / 64, T_TOK / 128, 1), 512>>>(g_hshared, sdw, out, 0);
}